// round 1
// baseline (speedup 1.0000x reference)
#include <cuda_runtime.h>
#include <math.h>

#define NN   50000
#define EE   1600000
#define HID  100
#define TLUT 8192
#define DMAXF 4.5f

// ---------------- device scratch (no allocations allowed) ----------------
__device__ float4 g_node[NN];        // packed (pos.xyz, z)
__device__ float4 g_agg[NN];         // scatter-add target
__device__ float2 g_lut[TLUT];       // radial MLP output w(d) * norm
__device__ float  g_h[(size_t)NN * 16]; // per-node 16-dim features

__device__ __forceinline__ float swishf(float s) {
    return s / (1.0f + expf(-s));
}

// ---------------- LUT: radial MLP tabulated over d in [0, 4.5] ----------------
__global__ void lut_kernel(const float* __restrict__ rw1, const float* __restrict__ rb1,
                           const float* __restrict__ rw2, const float* __restrict__ rb2,
                           const float* __restrict__ rw3, float normfac)
{
    __shared__ float h1s[HID * 64];          // per-thread hidden activations
    const int tid = threadIdx.x;             // blockDim.x == 64
    const int t = blockIdx.x * 64 + tid;
    float d = DMAXF * (float)t / (float)(TLUT - 1);

    // cosine basis, centers {0, 1.5, 3.0}, step 1.5
    float b[3];
    #pragma unroll
    for (int i = 0; i < 3; i++) {
        float diff = (d - 1.5f * (float)i) * (1.0f / 1.5f);
        float c = cosf(1.5707963267948966f * diff);
        b[i] = (fabsf(diff) < 1.0f) ? c * c : 0.0f;
    }

    // layer 1: 3 -> 100 (swish), keep in smem (thread-major, conflict-free)
    for (int j = 0; j < HID; j++) {
        float s = rb1[j] + b[0] * rw1[j] + b[1] * rw1[HID + j] + b[2] * rw1[2 * HID + j];
        h1s[j * 64 + tid] = swishf(s);
    }

    // layer 2: 100 -> 100 (swish), fused with layer 3: 100 -> 2
    float w0 = 0.f, w1 = 0.f;
    for (int jt = 0; jt < HID; jt += 20) {
        float acc[20];
        #pragma unroll
        for (int jj = 0; jj < 20; jj++) acc[jj] = rb2[jt + jj];
        for (int k = 0; k < HID; k++) {
            float hk = h1s[k * 64 + tid];
            const float4* rp = reinterpret_cast<const float4*>(rw2 + k * HID + jt); // 16B aligned
            #pragma unroll
            for (int q = 0; q < 5; q++) {
                float4 v = rp[q];
                acc[4 * q + 0] = fmaf(hk, v.x, acc[4 * q + 0]);
                acc[4 * q + 1] = fmaf(hk, v.y, acc[4 * q + 1]);
                acc[4 * q + 2] = fmaf(hk, v.z, acc[4 * q + 2]);
                acc[4 * q + 3] = fmaf(hk, v.w, acc[4 * q + 3]);
            }
        }
        #pragma unroll
        for (int jj = 0; jj < 20; jj++) {
            float h2 = swishf(acc[jj]);
            w0 = fmaf(h2, rw3[(jt + jj) * 2 + 0], w0);
            w1 = fmaf(h2, rw3[(jt + jj) * 2 + 1], w1);
        }
    }
    if (t < TLUT) g_lut[t] = make_float2(w0 * normfac, w1 * normfac);
}

// ---------------- pack nodes + zero accumulator ----------------
__global__ void pack_kernel(const float* __restrict__ pos, const float* __restrict__ z, int n)
{
    int i = blockIdx.x * blockDim.x + threadIdx.x;
    if (i >= n) return;
    g_node[i] = make_float4(pos[3 * i], pos[3 * i + 1], pos[3 * i + 2], z[i]);
    g_agg[i]  = make_float4(0.f, 0.f, 0.f, 0.f);
}

// ---------------- edge message + scatter-add ----------------
__global__ void edge_kernel(const int* __restrict__ ei, const float* __restrict__ ea, int e)
{
    int i = blockIdx.x * blockDim.x + threadIdx.x;
    if (i >= e) return;
    int s  = ei[i];
    int dn = ei[e + i];
    float4 ns = g_node[s];
    float4 nd = g_node[dn];
    float rx = ns.x - nd.x, ry = ns.y - nd.y, rz = ns.z - nd.z;
    float dist = sqrtf(fmaf(rx, rx, fmaf(ry, ry, rz * rz)) + 1e-12f);

    float ti = fminf(dist, DMAXF) * ((float)(TLUT - 1) / DMAXF);
    int i0 = (int)ti;
    if (i0 > TLUT - 2) i0 = TLUT - 2;
    float fr = ti - (float)i0;
    float2 la = g_lut[i0];
    float2 lb = g_lut[i0 + 1];
    float w0 = fmaf(fr, lb.x - la.x, la.x);
    float w1 = fmaf(fr, lb.y - la.y, la.y);

    float ev = ea[i];
    float c0 = w0 * ev, c1 = w1 * ev;
    float* ap = reinterpret_cast<float*>(&g_agg[dn]);
    atomicAdd(ap + 0, c0 * ns.x);
    atomicAdd(ap + 1, c0 * ns.y);
    atomicAdd(ap + 2, c0 * ns.z);
    atomicAdd(ap + 3, c1 * ns.w);
}

// ---------------- per-node MLP: relu(agg) -> 32 -> 16 -> relu ----------------
__global__ void node_kernel(const float* __restrict__ lw1, const float* __restrict__ lb1,
                            const float* __restrict__ lw2, const float* __restrict__ lb2, int n)
{
    __shared__ float sw1[128], sb1[32], sw2[512], sb2[16];
    int tid = threadIdx.x;
    for (int i = tid; i < 128; i += blockDim.x) sw1[i] = lw1[i];
    for (int i = tid; i < 512; i += blockDim.x) sw2[i] = lw2[i];
    if (tid < 32) sb1[tid] = lb1[tid];
    if (tid < 16) sb2[tid] = lb2[tid];
    __syncthreads();

    int i = blockIdx.x * blockDim.x + tid;
    if (i >= n) return;
    float4 a = g_agg[i];
    float a0 = fmaxf(a.x, 0.f), a1 = fmaxf(a.y, 0.f), a2 = fmaxf(a.z, 0.f), a3 = fmaxf(a.w, 0.f);

    float tb[32];
    #pragma unroll
    for (int j = 0; j < 32; j++) {
        float s = sb1[j] + a0 * sw1[j] + a1 * sw1[32 + j] + a2 * sw1[64 + j] + a3 * sw1[96 + j];
        tb[j] = fmaxf(s, 0.f);
    }
    float h[16];
    #pragma unroll
    for (int f = 0; f < 16; f++) h[f] = sb2[f];
    #pragma unroll
    for (int j = 0; j < 32; j++) {
        float tj = tb[j];
        #pragma unroll
        for (int f = 0; f < 16; f++) h[f] = fmaf(tj, sw2[j * 16 + f], h[f]);
    }
    float4* hp = reinterpret_cast<float4*>(g_h + (size_t)i * 16);
    hp[0] = make_float4(fmaxf(h[0],0.f),  fmaxf(h[1],0.f),  fmaxf(h[2],0.f),  fmaxf(h[3],0.f));
    hp[1] = make_float4(fmaxf(h[4],0.f),  fmaxf(h[5],0.f),  fmaxf(h[6],0.f),  fmaxf(h[7],0.f));
    hp[2] = make_float4(fmaxf(h[8],0.f),  fmaxf(h[9],0.f),  fmaxf(h[10],0.f), fmaxf(h[11],0.f));
    hp[3] = make_float4(fmaxf(h[12],0.f), fmaxf(h[13],0.f), fmaxf(h[14],0.f), fmaxf(h[15],0.f));
}

// ---------------- mean-pool per graph (batch sorted) + head ----------------
__device__ __forceinline__ int bget(const void* b, int k, bool is64) {
    return is64 ? (int)((const long long*)b)[k] : ((const int*)b)[k];
}

__global__ void pool_head_kernel(const void* __restrict__ batch, int n,
                                 const float* __restrict__ fw1, const float* __restrict__ fb1,
                                 const float* __restrict__ fw2, const float* __restrict__ fb2,
                                 float* __restrict__ out)
{
    const int g = blockIdx.x;  // one block per graph; blockDim.x == 256
    // dtype detect: int64 little-endian values < 2^32 -> int32 view at odd idx n-1 is 0.
    bool is64 = (((const int*)batch)[n - 1] == 0);

    // lower_bound(g), lower_bound(g+1) over sorted batch
    int lo = 0, hi = n;
    while (lo < hi) { int mid = (lo + hi) >> 1; if (bget(batch, mid, is64) < g) lo = mid + 1; else hi = mid; }
    int start = lo;
    hi = n;
    while (lo < hi) { int mid = (lo + hi) >> 1; if (bget(batch, mid, is64) < g + 1) lo = mid + 1; else hi = mid; }
    int end = lo;

    float acc[16];
    #pragma unroll
    for (int f = 0; f < 16; f++) acc[f] = 0.f;
    for (int i = start + threadIdx.x; i < end; i += blockDim.x) {
        const float4* hp = reinterpret_cast<const float4*>(g_h + (size_t)i * 16);
        float4 v0 = hp[0], v1 = hp[1], v2 = hp[2], v3 = hp[3];
        acc[0] += v0.x;  acc[1] += v0.y;  acc[2]  += v0.z;  acc[3]  += v0.w;
        acc[4] += v1.x;  acc[5] += v1.y;  acc[6]  += v1.z;  acc[7]  += v1.w;
        acc[8] += v2.x;  acc[9] += v2.y;  acc[10] += v2.z;  acc[11] += v2.w;
        acc[12]+= v3.x;  acc[13]+= v3.y;  acc[14] += v3.z;  acc[15] += v3.w;
    }
    #pragma unroll
    for (int f = 0; f < 16; f++) {
        #pragma unroll
        for (int o = 16; o; o >>= 1) acc[f] += __shfl_xor_sync(0xffffffffu, acc[f], o);
    }
    __shared__ float sred[8][16];
    int wid = threadIdx.x >> 5, lane = threadIdx.x & 31;
    if (lane == 0) {
        #pragma unroll
        for (int f = 0; f < 16; f++) sred[wid][f] = acc[f];
    }
    __syncthreads();
    if (threadIdx.x == 0) {
        int cnt = end - start;
        float inv = 1.0f / (float)(cnt > 0 ? cnt : 1);
        float p[16];
        #pragma unroll
        for (int f = 0; f < 16; f++) {
            float s = 0.f;
            #pragma unroll
            for (int w = 0; w < 8; w++) s += sred[w][f];
            p[f] = s * inv;
        }
        float o0 = fb2[0], o1 = fb2[1], o2 = fb2[2];
        #pragma unroll
        for (int j = 0; j < 32; j++) {
            float s = fb1[j];
            #pragma unroll
            for (int k = 0; k < 16; k++) s = fmaf(p[k], fw1[k * 32 + j], s);
            s = fmaxf(s, 0.f);
            o0 = fmaf(s, fw2[j * 3 + 0], o0);
            o1 = fmaf(s, fw2[j * 3 + 1], o1);
            o2 = fmaf(s, fw2[j * 3 + 2], o2);
        }
        out[3 * g + 0] = o0;
        out[3 * g + 1] = o1;
        out[3 * g + 2] = o2;
    }
}

// ---------------- launch ----------------
extern "C" void kernel_launch(void* const* d_in, const int* in_sizes, int n_in,
                              void* d_out, int out_size)
{
    const float* pos = (const float*)d_in[0];
    const float* z   = (const float*)d_in[1];
    const float* ea  = (const float*)d_in[2];
    const int*   ei  = (const int*)d_in[3];
    const void*  bat = d_in[4];
    const float* rw1 = (const float*)d_in[5];
    const float* rb1 = (const float*)d_in[6];
    const float* rw2 = (const float*)d_in[7];
    const float* rb2 = (const float*)d_in[8];
    const float* rw3 = (const float*)d_in[9];
    const float* lw1 = (const float*)d_in[10];
    const float* lb1 = (const float*)d_in[11];
    const float* lw2 = (const float*)d_in[12];
    const float* lb2 = (const float*)d_in[13];
    const float* fw1 = (const float*)d_in[14];
    const float* fb1 = (const float*)d_in[15];
    const float* fw2 = (const float*)d_in[16];
    const float* fb2 = (const float*)d_in[17];

    int N = in_sizes[1];          // z count
    int E = in_sizes[2];          // edge_attr count
    int G = out_size / 3;

    float normfac = sqrtf((float)N / (float)E);   // 1/sqrt(E/N), folded into LUT

    lut_kernel<<<TLUT / 64, 64>>>(rw1, rb1, rw2, rb2, rw3, normfac);
    pack_kernel<<<(N + 255) / 256, 256>>>(pos, z, N);
    edge_kernel<<<(E + 255) / 256, 256>>>(ei, ea, E);
    node_kernel<<<(N + 255) / 256, 256>>>(lw1, lb1, lw2, lb2, N);
    pool_head_kernel<<<G, 256>>>(bat, N, fw1, fb1, fw2, fb2, (float*)d_out);
}

// round 3
// speedup vs baseline: 1.6587x; 1.6587x over previous
#include <cuda_runtime.h>
#include <math.h>

#define NN   50000
#define HID  100
#define TLUT 4096
#define DMAXF 4.5f

// ---------------- device scratch (no allocations allowed) ----------------
__device__ float4 g_node[NN];        // packed (pos.xyz, z)
__device__ float4 g_agg[NN];         // scatter-add target
__device__ float2 g_lut[TLUT];       // radial MLP output w(d) * norm

__device__ __forceinline__ float swishf(float s) {
    return s / (1.0f + expf(-s));
}

// ---------------- LUT: radial MLP tabulated over d in [0, 4.5] ----------------
// 2 threads per table entry (split the k-sum of layer 2), 32 entries per block.
__global__ void lut_kernel(const float* __restrict__ rw1, const float* __restrict__ rb1,
                           const float* __restrict__ rw2, const float* __restrict__ rb2,
                           const float* __restrict__ rw3, float normfac)
{
    __shared__ float h1s[HID][34];           // [k][entry], padded vs conflicts
    const int tid   = threadIdx.x;           // blockDim.x == 64
    const int el    = tid >> 1;              // entry within block (0..31)
    const int half  = tid & 1;               // which k-half this lane owns
    const int t     = blockIdx.x * 32 + el;  // table index
    float d = DMAXF * (float)t / (float)(TLUT - 1);

    // cosine basis, centers {0, 1.5, 3.0}, step 1.5
    float b0, b1, b2;
    {
        float bb[3];
        #pragma unroll
        for (int i = 0; i < 3; i++) {
            float diff = (d - 1.5f * (float)i) * (1.0f / 1.5f);
            float c = cosf(1.5707963267948966f * diff);
            bb[i] = (fabsf(diff) < 1.0f) ? c * c : 0.0f;
        }
        b0 = bb[0]; b1 = bb[1]; b2 = bb[2];
    }

    // layer 1: 3 -> 100 (swish). Each lane computes its own k-half and
    // reads back only what it wrote -> no sync needed.
    const int k0 = half * 50;
    for (int j = k0; j < k0 + 50; j++) {
        float s = rb1[j] + b0 * rw1[j] + b1 * rw1[HID + j] + b2 * rw1[2 * HID + j];
        h1s[j][el] = swishf(s);
    }

    // layer 2 (100->100 swish) fused with layer 3 (100->2); k-sum split across pair
    float w0 = 0.f, w1 = 0.f;
    for (int jt = 0; jt < HID; jt += 20) {
        float acc[20];
        #pragma unroll
        for (int jj = 0; jj < 20; jj++) acc[jj] = half ? 0.f : rb2[jt + jj];
        for (int k = k0; k < k0 + 50; k++) {
            float hk = h1s[k][el];
            const float4* rp = reinterpret_cast<const float4*>(rw2 + k * HID + jt);
            #pragma unroll
            for (int q = 0; q < 5; q++) {
                float4 v = rp[q];
                acc[4 * q + 0] = fmaf(hk, v.x, acc[4 * q + 0]);
                acc[4 * q + 1] = fmaf(hk, v.y, acc[4 * q + 1]);
                acc[4 * q + 2] = fmaf(hk, v.z, acc[4 * q + 2]);
                acc[4 * q + 3] = fmaf(hk, v.w, acc[4 * q + 3]);
            }
        }
        // pair reduce: lanes (2e, 2e+1) combine k-halves
        #pragma unroll
        for (int jj = 0; jj < 20; jj++) acc[jj] += __shfl_xor_sync(0xffffffffu, acc[jj], 1);
        // both lanes hold full sums; split the jj work for layer 3
        #pragma unroll
        for (int jj = 0; jj < 20; jj += 2) {
            int j = jt + jj + half;
            float h2 = swishf(acc[jj + half]);
            w0 = fmaf(h2, rw3[j * 2 + 0], w0);
            w1 = fmaf(h2, rw3[j * 2 + 1], w1);
        }
    }
    w0 += __shfl_xor_sync(0xffffffffu, w0, 1);
    w1 += __shfl_xor_sync(0xffffffffu, w1, 1);
    if (half == 0 && t < TLUT) g_lut[t] = make_float2(w0 * normfac, w1 * normfac);
}

// ---------------- pack nodes + zero accumulator ----------------
__global__ void pack_kernel(const float* __restrict__ pos, const float* __restrict__ z, int n)
{
    int i = blockIdx.x * blockDim.x + threadIdx.x;
    if (i >= n) return;
    g_node[i] = make_float4(pos[3 * i], pos[3 * i + 1], pos[3 * i + 2], z[i]);
    g_agg[i]  = make_float4(0.f, 0.f, 0.f, 0.f);
}

// ---------------- edge message + vector scatter-add ----------------
__device__ __forceinline__ void edge_one(int s, int dn, float ev)
{
    float4 ns = __ldg(&g_node[s]);
    float4 nd = __ldg(&g_node[dn]);
    float rx = ns.x - nd.x, ry = ns.y - nd.y, rz = ns.z - nd.z;
    float dist = sqrtf(fmaf(rx, rx, fmaf(ry, ry, rz * rz)) + 1e-12f);

    float ti = fminf(dist, DMAXF) * ((float)(TLUT - 1) / DMAXF);
    int i0 = (int)ti;
    if (i0 > TLUT - 2) i0 = TLUT - 2;
    float fr = ti - (float)i0;
    float2 la = __ldg(&g_lut[i0]);
    float2 lb = __ldg(&g_lut[i0 + 1]);
    float w0 = fmaf(fr, lb.x - la.x, la.x);
    float w1 = fmaf(fr, lb.y - la.y, la.y);

    float c0 = w0 * ev, c1 = w1 * ev;
    float vx = c0 * ns.x, vy = c0 * ns.y, vz = c0 * ns.z, vw = c1 * ns.w;
    float* ap = reinterpret_cast<float*>(&g_agg[dn]);
    asm volatile("red.global.add.v4.f32 [%0], {%1, %2, %3, %4};"
                 :: "l"(ap), "f"(vx), "f"(vy), "f"(vz), "f"(vw)
                 : "memory");
}

// 4 edges per thread, vectorized index/attr loads.
__global__ void edge_kernel(const int* __restrict__ ei, const float* __restrict__ ea,
                            int e4, int e)
{
    int i = blockIdx.x * blockDim.x + threadIdx.x;
    if (i >= e4) return;
    int4   s4 = __ldg(reinterpret_cast<const int4*>(ei) + i);
    int4   d4 = __ldg(reinterpret_cast<const int4*>(ei + e) + i);
    float4 ev = __ldg(reinterpret_cast<const float4*>(ea) + i);
    edge_one(s4.x, d4.x, ev.x);
    edge_one(s4.y, d4.y, ev.y);
    edge_one(s4.z, d4.z, ev.z);
    edge_one(s4.w, d4.w, ev.w);
    if (i == 0) {                            // tail for E not divisible by 4
        for (int last = e4 * 4; last < e; last++)
            edge_one(ei[last], ei[e + last], ea[last]);
    }
}

// ---------------- fused node MLP + mean-pool per graph + head ----------------
__device__ __forceinline__ int bget(const void* b, int k, bool is64) {
    return is64 ? (int)((const long long*)b)[k] : ((const int*)b)[k];
}

__global__ void pool_head_kernel(const void* __restrict__ batch, int n,
                                 const float* __restrict__ lw1, const float* __restrict__ lb1,
                                 const float* __restrict__ lw2, const float* __restrict__ lb2,
                                 const float* __restrict__ fw1, const float* __restrict__ fb1,
                                 const float* __restrict__ fw2, const float* __restrict__ fb2,
                                 float* __restrict__ out)
{
    __shared__ float sw1[128], sb1[32], sw2[512], sb2[16];
    const int g = blockIdx.x;                // one block per graph; blockDim.x == 256
    const int tid = threadIdx.x;
    for (int i = tid; i < 128; i += blockDim.x) sw1[i] = lw1[i];
    for (int i = tid; i < 512; i += blockDim.x) sw2[i] = lw2[i];
    if (tid < 32) sb1[tid] = lb1[tid];
    if (tid < 16) sb2[tid] = lb2[tid];
    __syncthreads();

    // dtype detect: int64 little-endian values < 2^32 -> int32 view at odd idx n-1 is 0.
    bool is64 = (((const int*)batch)[n - 1] == 0);

    // segment bounds: lower_bound(g), lower_bound(g+1) on sorted batch
    int lo = 0, hi = n;
    while (lo < hi) { int mid = (lo + hi) >> 1; if (bget(batch, mid, is64) < g) lo = mid + 1; else hi = mid; }
    int start = lo;
    hi = n;
    while (lo < hi) { int mid = (lo + hi) >> 1; if (bget(batch, mid, is64) < g + 1) lo = mid + 1; else hi = mid; }
    int end = lo;

    float acc[16];
    #pragma unroll
    for (int f = 0; f < 16; f++) acc[f] = 0.f;

    for (int i = start + tid; i < end; i += blockDim.x) {
        float4 a = __ldg(&g_agg[i]);
        float a0 = fmaxf(a.x, 0.f), a1 = fmaxf(a.y, 0.f), a2 = fmaxf(a.z, 0.f), a3 = fmaxf(a.w, 0.f);
        float h[16];
        #pragma unroll
        for (int f = 0; f < 16; f++) h[f] = sb2[f];
        #pragma unroll
        for (int j = 0; j < 32; j++) {
            float s = sb1[j] + a0 * sw1[j] + a1 * sw1[32 + j] + a2 * sw1[64 + j] + a3 * sw1[96 + j];
            s = fmaxf(s, 0.f);
            #pragma unroll
            for (int f = 0; f < 16; f++) h[f] = fmaf(s, sw2[j * 16 + f], h[f]);
        }
        #pragma unroll
        for (int f = 0; f < 16; f++) acc[f] += fmaxf(h[f], 0.f);
    }

    #pragma unroll
    for (int f = 0; f < 16; f++) {
        #pragma unroll
        for (int o = 16; o; o >>= 1) acc[f] += __shfl_xor_sync(0xffffffffu, acc[f], o);
    }
    __shared__ float sred[8][16];
    int wid = tid >> 5, lane = tid & 31;
    if (lane == 0) {
        #pragma unroll
        for (int f = 0; f < 16; f++) sred[wid][f] = acc[f];
    }
    __syncthreads();
    if (tid == 0) {
        int cnt = end - start;
        float inv = 1.0f / (float)(cnt > 0 ? cnt : 1);
        float p[16];
        #pragma unroll
        for (int f = 0; f < 16; f++) {
            float s = 0.f;
            #pragma unroll
            for (int w = 0; w < 8; w++) s += sred[w][f];
            p[f] = s * inv;
        }
        float o0 = fb2[0], o1 = fb2[1], o2 = fb2[2];
        #pragma unroll
        for (int j = 0; j < 32; j++) {
            float s = fb1[j];
            #pragma unroll
            for (int k = 0; k < 16; k++) s = fmaf(p[k], fw1[k * 32 + j], s);
            s = fmaxf(s, 0.f);
            o0 = fmaf(s, fw2[j * 3 + 0], o0);
            o1 = fmaf(s, fw2[j * 3 + 1], o1);
            o2 = fmaf(s, fw2[j * 3 + 2], o2);
        }
        out[3 * g + 0] = o0;
        out[3 * g + 1] = o1;
        out[3 * g + 2] = o2;
    }
}

// ---------------- launch ----------------
extern "C" void kernel_launch(void* const* d_in, const int* in_sizes, int n_in,
                              void* d_out, int out_size)
{
    const float* pos = (const float*)d_in[0];
    const float* z   = (const float*)d_in[1];
    const float* ea  = (const float*)d_in[2];
    const int*   ei  = (const int*)d_in[3];
    const void*  bat = d_in[4];
    const float* rw1 = (const float*)d_in[5];
    const float* rb1 = (const float*)d_in[6];
    const float* rw2 = (const float*)d_in[7];
    const float* rb2 = (const float*)d_in[8];
    const float* rw3 = (const float*)d_in[9];
    const float* lw1 = (const float*)d_in[10];
    const float* lb1 = (const float*)d_in[11];
    const float* lw2 = (const float*)d_in[12];
    const float* lb2 = (const float*)d_in[13];
    const float* fw1 = (const float*)d_in[14];
    const float* fb1 = (const float*)d_in[15];
    const float* fw2 = (const float*)d_in[16];
    const float* fb2 = (const float*)d_in[17];

    int N = in_sizes[1];          // z count
    int E = in_sizes[2];          // edge_attr count
    int G = out_size / 3;

    float normfac = sqrtf((float)N / (float)E);   // 1/sqrt(E/N), folded into LUT

    lut_kernel<<<TLUT / 32, 64>>>(rw1, rb1, rw2, rb2, rw3, normfac);
    pack_kernel<<<(N + 255) / 256, 256>>>(pos, z, N);
    int e4 = E / 4;
    edge_kernel<<<(e4 + 255) / 256, 256>>>(ei, ea, e4, E);
    pool_head_kernel<<<G, 256>>>(bat, N, lw1, lb1, lw2, lb2,
                                 fw1, fb1, fw2, fb2, (float*)d_out);
}